// round 15
// baseline (speedup 1.0000x reference)
#include <cuda_runtime.h>
#include <cuda_bf16.h>
#include <math.h>
#include <math_constants.h>
#include <cstdint>

// Problem constants
#define VOCABN 100000
#define EMBED  100
#define NOISEN 10
#define CIN    110
#define HID    128
#define BATCH  2048

// GEMM tiling
#define NCH2 1563               // ceil(100000/64): 64-wide CTA slabs
#define NCHP (2 * NCH2)         // partials per row (two 32-col halves per CTA)
#define MT16 16                 // 128-row A tiles
#define TILE_BYTES 32768        // 128x128 bf16 tile

#define LOG2E 1.4426950408889634f

// LSTM kernel tiling
#define A_ROWS 16
#define WPAD   111

// ---------------------------------------------------------------------------
// Scratch (static __device__, no allocations)
// ---------------------------------------------------------------------------
__device__ __align__(16) char g_A[MT16 * TILE_BYTES];            // 512 KB (log2e-scaled)
__device__ float g_psum[(size_t)BATCH * NCHP];                   // 25.6 MB
__device__ float g_invZ[BATCH];

__device__ __forceinline__ float sigm(float v) { return 1.0f / (1.0f + expf(-v)); }

__device__ __forceinline__ uint32_t smem_to_u32(const void* p) {
    uint32_t a;
    asm("{ .reg .u64 t; cvta.to.shared.u64 t, %1; cvt.u32.u64 %0, t; }" : "=r"(a) : "l"(p));
    return a;
}

__device__ __forceinline__ float ex2f(float x) {
    float r;
    asm("ex2.approx.f32 %0, %1;" : "=f"(r) : "f"(x));
    return r;
}

// Blocked-atom SW128 byte offset inside a 128x128 bf16 tile (16 atom-rows x 2 atom-cols)
__host__ __device__ __forceinline__ uint32_t tile_off(int row, int col) {
    return (uint32_t)((((row >> 3) + ((col >> 6) << 4)) << 10) +
                      ((row & 7) << 7) + ((((col & 63) << 1)) ^ ((row & 7) << 4)));
}

// Same swizzle for a 64x128 tile (8 atom-rows x 2 atom-cols)
__device__ __forceinline__ uint32_t tile_off64(int row, int col) {
    return (uint32_t)((((row >> 3) + ((col >> 6) << 3)) << 10) +
                      ((row & 7) << 7) + ((((col & 63) << 1)) ^ ((row & 7) << 4)));
}

__device__ __forceinline__ void ldsm_x4(uint32_t* r, uint32_t addr) {
    asm volatile("ldmatrix.sync.aligned.m8n8.x4.shared.b16 {%0,%1,%2,%3}, [%4];"
                 : "=r"(r[0]), "=r"(r[1]), "=r"(r[2]), "=r"(r[3]) : "r"(addr));
}

__device__ __forceinline__ void mma16816(float* c, const uint32_t* a, uint32_t b0, uint32_t b1) {
    asm volatile(
        "mma.sync.aligned.m16n8k16.row.col.f32.bf16.bf16.f32 "
        "{%0,%1,%2,%3}, {%4,%5,%6,%7}, {%8,%9}, {%0,%1,%2,%3};"
        : "+f"(c[0]), "+f"(c[1]), "+f"(c[2]), "+f"(c[3])
        : "r"(a[0]), "r"(a[1]), "r"(a[2]), "r"(a[3]), "r"(b0), "r"(b1));
}

__device__ __forceinline__ void cp_async16(uint32_t saddr, const void* gaddr) {
    asm volatile("cp.async.cg.shared.global [%0], [%1], 16;" :: "r"(saddr), "l"(gaddr));
}
#define CP_COMMIT() asm volatile("cp.async.commit_group;" ::: "memory")
#define CP_WAIT0()  asm volatile("cp.async.wait_group 0;" ::: "memory")

// K-step address transform for the hoisted A ldsm base (full 128x128 tile)
#define KADDR(base, ks) ((((ks) >= 4) ? ((base) + 16384u) : (base)) ^ (uint32_t)(((ks) & 3) << 5))

// Exchange a float2 with lane^r
__device__ __forceinline__ float2 shfl_xor_f2(float2 v, int r) {
    double d = __shfl_xor_sync(0xffffffffu, *reinterpret_cast<double*>(&v), r);
    return *reinterpret_cast<float2*>(&d);
}

// ---------------------------------------------------------------------------
// Kernel A: embedding + noise + LSTM step -> swizzled bf16 A tiles directly
// (values pre-scaled by log2(e)).
// ---------------------------------------------------------------------------
__global__ void lstm_kernel(const int* __restrict__ x,
                            const float* __restrict__ noise,
                            const float* __restrict__ emb,
                            const float* __restrict__ W_ih,
                            const float* __restrict__ b_ih,
                            const float* __restrict__ b_hh) {
    extern __shared__ float sm[];
    float* Wsm = sm;                       // [384][WPAD]
    float* Csm = sm + 384 * WPAD;          // [A_ROWS][CIN]

    const int t = threadIdx.x;
    const int row0 = blockIdx.x * A_ROWS;

    for (int idx = t; idx < 384 * CIN; idx += 256) {
        int r = idx / CIN;
        int k = idx - r * CIN;
        int gr = (r < 128) ? r : (r + 128);   // skip dead f block
        Wsm[r * WPAD + k] = W_ih[gr * CIN + k];
    }
    for (int idx = t; idx < A_ROWS * CIN; idx += 256) {
        int r = idx / CIN;
        int k = idx - r * CIN;
        int brow = row0 + r;
        float v = (k < EMBED) ? emb[(size_t)x[brow] * EMBED + k]
                              : noise[brow * NOISEN + (k - EMBED)];
        Csm[r * CIN + k] = v;
    }
    __syncthreads();

    const int j = t & 127;
    const int rhalf = t >> 7;
    const float bi = b_ih[j]       + b_hh[j];
    const float bg = b_ih[256 + j] + b_hh[256 + j];
    const float bo = b_ih[384 + j] + b_hh[384 + j];

    const float* wi = &Wsm[j * WPAD];
    const float* wg = &Wsm[(128 + j) * WPAD];
    const float* wo = &Wsm[(256 + j) * WPAD];

    for (int rr = 0; rr < A_ROWS / 2; rr++) {
        int r = rhalf * (A_ROWS / 2) + rr;
        const float* c = &Csm[r * CIN];
        float ai = bi, ag = bg, ao = bo;
        #pragma unroll 2
        for (int k = 0; k < CIN; k++) {
            float cv = c[k];
            ai = fmaf(wi[k], cv, ai);
            ag = fmaf(wg[k], cv, ag);
            ao = fmaf(wo[k], cv, ao);
        }
        float cc = sigm(ai) * tanhf(ag);
        float h  = sigm(ao) * tanhf(cc);

        // Pre-scale by log2(e); pack adjacent cols and store swizzled bf16x2
        float hs = h * LOG2E;
        float hn = __shfl_xor_sync(0xffffffffu, hs, 1);
        if (!(t & 1)) {
            __nv_bfloat162 h2 = __floats2bfloat162_rn(hs, hn);
            int row = row0 + r;
            uint32_t off = (uint32_t)(row >> 7) * TILE_BYTES + tile_off(row & 127, j);
            *reinterpret_cast<uint32_t*>(g_A + off) = *reinterpret_cast<uint32_t*>(&h2);
        }
    }
}

// ---------------------------------------------------------------------------
// GEMM: CTA owns a 64-col vocab slab; B staged from fc_w (fp32->bf16 inline),
// then held entirely in registers. Warps 4(M)x2(N), warp tile 32x32.
// A double-buffered via cp.async. PHASE==1: sumexp partials. PHASE==2: probs.
// ---------------------------------------------------------------------------
#define OFF_BS    0              // 16 KB staged B slab (64 rows x 128 cols bf16)
#define OFF_A     16384          // 2 x 32 KB
#define OFF_BIAS  81920          // 64 floats
#define SMEM_GEMM 82176

template <int PHASE>
__global__ __launch_bounds__(256, 2) void gemm_tc(const float* __restrict__ fc_w,
                                                  const float* __restrict__ fc_b,
                                                  float* __restrict__ out) {
    extern __shared__ char smem[];
    const int t = threadIdx.x, wid = t >> 5, lane = t & 31;
    const int vb = blockIdx.x;          // 64-col slab id
    const uint32_t sb = smem_to_u32(smem);

    const int wm = wid >> 1;      // 0..3 : 32-row slab
    const int wn = wid & 1;       // 0..1 : 32-col slab
    const int g = lane >> 2, t4 = lane & 3;

    // A[0] prefetch first (longest latency)
    #pragma unroll
    for (int i = 0; i < 8; i++)
        cp_async16(sb + OFF_A + t * 16 + i * 4096, g_A + t * 16 + i * 4096);
    CP_COMMIT();

    // Stage B slab: fc_w rows vb*64..+63, fp32 -> bf16, swizzled 64x128 tile.
    {
        const int row = t >> 2;
        const int v = vb * 64 + row;
        const bool valid = (v < VOCABN);
        const float4* src = reinterpret_cast<const float4*>(fc_w + (size_t)v * HID);
        #pragma unroll
        for (int i = 0; i < 4; i++) {
            int c8 = (t & 3) + 4 * i;      // 8-col chunk 0..15
            float4 w0, w1;
            if (valid) { w0 = src[c8 * 2]; w1 = src[c8 * 2 + 1]; }
            else       { w0 = w1 = make_float4(0.f, 0.f, 0.f, 0.f); }
            __nv_bfloat162 p0 = __floats2bfloat162_rn(w0.x, w0.y);
            __nv_bfloat162 p1 = __floats2bfloat162_rn(w0.z, w0.w);
            __nv_bfloat162 p2 = __floats2bfloat162_rn(w1.x, w1.y);
            __nv_bfloat162 p3 = __floats2bfloat162_rn(w1.z, w1.w);
            uint4 packed = make_uint4(*reinterpret_cast<uint32_t*>(&p0),
                                      *reinterpret_cast<uint32_t*>(&p1),
                                      *reinterpret_cast<uint32_t*>(&p2),
                                      *reinterpret_cast<uint32_t*>(&p3));
            *reinterpret_cast<uint4*>(smem + OFF_BS + tile_off64(row, c8 * 8)) = packed;
        }
    }
    if (t < 64) {
        int gc = vb * 64 + t;
        reinterpret_cast<float*>(smem + OFF_BIAS)[t] =
            (gc < VOCABN) ? LOG2E * fc_b[gc] : -CUDART_INF_F;
    }
    __syncthreads();

    // Lane mapping for ldsm
    const int sub = lane >> 3, rr = lane & 7;
    const int lrow = ((sub & 1) << 3) + rr;
    const int colp = (sub >> 1) << 3;

    // Load this warp's B operand into registers: 8 ks x 2 n16-blocks x 4 regs
    uint32_t bf[8][2][4];
    {
        const int brow0 = wn * 32;
        #pragma unroll
        for (int ks = 0; ks < 8; ks++)
            #pragma unroll
            for (int nbb = 0; nbb < 2; nbb++)
                ldsm_x4(bf[ks][nbb],
                        sb + OFF_BS + tile_off64(brow0 + nbb * 16 + lrow, ks * 16 + colp));
    }

    const int am0 = wm * 32;
    const uint32_t baseA0 = sb + OFF_A + tile_off(am0 + lrow, colp);
    const float* bias = reinterpret_cast<const float*>(smem + OFF_BIAS);
    CP_WAIT0();
    __syncthreads();

    const bool full_tile = (vb < NCH2 - 1);

    for (int mt = 0; mt < MT16; mt++) {
        if (mt + 1 < MT16) {
            uint32_t dst = sb + OFF_A + ((mt + 1) & 1) * TILE_BYTES;
            const char* src = g_A + (size_t)(mt + 1) * TILE_BYTES;
            #pragma unroll
            for (int i = 0; i < 8; i++)
                cp_async16(dst + t * 16 + i * 4096, src + t * 16 + i * 4096);
            CP_COMMIT();
        }
        const int mbase = mt * 128;
        const uint32_t baseA = baseA0 + (mt & 1) * TILE_BYTES;

        // acc init from scaled bias (re-read from smem each tile; saves regs)
        float acc[2][4][4];
        #pragma unroll
        for (int nb = 0; nb < 4; nb++) {
            float2 bv = *reinterpret_cast<const float2*>(bias + wn * 32 + nb * 8 + t4 * 2);
            #pragma unroll
            for (int mb = 0; mb < 2; mb++) {
                acc[mb][nb][0] = bv.x;
                acc[mb][nb][1] = bv.y;
                acc[mb][nb][2] = bv.x;
                acc[mb][nb][3] = bv.y;
            }
        }

        #pragma unroll
        for (int ks = 0; ks < 8; ks++) {
            uint32_t a[2][4];
            #pragma unroll
            for (int mb = 0; mb < 2; mb++)
                ldsm_x4(a[mb], KADDR(baseA + mb * 2048, ks));
            #pragma unroll
            for (int mb = 0; mb < 2; mb++)
                #pragma unroll
                for (int nbb = 0; nbb < 2; nbb++) {
                    mma16816(acc[mb][2 * nbb],     a[mb], bf[ks][nbb][0], bf[ks][nbb][2]);
                    mma16816(acc[mb][2 * nbb + 1], a[mb], bf[ks][nbb][1], bf[ks][nbb][3]);
                }
        }

        if (PHASE == 1) {
            // ---- sumexp partial per (row, 32-col half) ----
            #pragma unroll
            for (int mb = 0; mb < 2; mb++) {
                #pragma unroll
                for (int h = 0; h < 2; h++) {
                    int rl = am0 + mb * 16 + h * 8 + g;
                    float s = 0.f;
                    #pragma unroll
                    for (int nb = 0; nb < 4; nb++)
                        s += ex2f(acc[mb][nb][h * 2]) + ex2f(acc[mb][nb][h * 2 + 1]);
                    s += __shfl_xor_sync(0xffffffffu, s, 1);
                    s += __shfl_xor_sync(0xffffffffu, s, 2);
                    if (t4 == 0)
                        g_psum[(size_t)(mbase + rl) * NCHP + vb * 2 + wn] = s;
                }
            }
        } else {
            // ---- probs: p = ex2(acc) * invZ; 4-lane transpose -> STG.128 ----
            float iz[2][2];
            #pragma unroll
            for (int mb = 0; mb < 2; mb++)
                #pragma unroll
                for (int h = 0; h < 2; h++)
                    iz[mb][h] = __ldg(&g_invZ[mbase + am0 + mb * 16 + h * 8 + g]);

            const int b0 = t4 & 1, b1 = (t4 >> 1) & 1;

            #pragma unroll
            for (int mb = 0; mb < 2; mb++) {
                #pragma unroll
                for (int h = 0; h < 2; h++) {
                    int rl = am0 + mb * 16 + h * 8 + g;
                    size_t rb = (size_t)(mbase + rl) * VOCABN + vb * 64 + wn * 32;

                    float2 pv[4];
                    #pragma unroll
                    for (int nb = 0; nb < 4; nb++) {
                        pv[nb].x = ex2f(acc[mb][nb][h * 2])     * iz[mb][h];
                        pv[nb].y = ex2f(acc[mb][nb][h * 2 + 1]) * iz[mb][h];
                    }

                    // Stage 1 (xor 1, bit0): trade slots whose bit0 != b0
                    {
                        float2 s0 = b0 ? pv[0] : pv[1];
                        float2 s1 = b0 ? pv[2] : pv[3];
                        float2 r0 = shfl_xor_f2(s0, 1);
                        float2 r1 = shfl_xor_f2(s1, 1);
                        if (b0) { pv[0] = r0; pv[2] = r1; }
                        else    { pv[1] = r0; pv[3] = r1; }
                    }
                    // Stage 2 (xor 2, bit1): trade slots whose bit1 != b1
                    {
                        float2 s0 = b1 ? pv[0] : pv[2];
                        float2 s1 = b1 ? pv[1] : pv[3];
                        float2 r0 = shfl_xor_f2(s0, 2);
                        float2 r1 = shfl_xor_f2(s1, 2);
                        if (b1) { pv[0] = r0; pv[1] = r1; }
                        else    { pv[2] = r0; pv[3] = r1; }
                    }
                    // Lane t4 now holds 8 contiguous cols at t4*8
                    float4 q0 = make_float4(pv[0].x, pv[0].y, pv[1].x, pv[1].y);
                    float4 q1 = make_float4(pv[2].x, pv[2].y, pv[3].x, pv[3].y);
                    if (full_tile) {
                        __stcs(reinterpret_cast<float4*>(out + rb + t4 * 8), q0);
                        __stcs(reinterpret_cast<float4*>(out + rb + t4 * 8 + 4), q1);
                    } else {
                        int gcol = vb * 64 + wn * 32 + t4 * 8;
                        if (gcol < VOCABN)
                            __stcs(reinterpret_cast<float4*>(out + rb + t4 * 8), q0);
                        if (gcol + 4 < VOCABN)
                            __stcs(reinterpret_cast<float4*>(out + rb + t4 * 8 + 4), q1);
                    }
                }
            }
        }
        CP_WAIT0();
        __syncthreads();
    }
}

// ---------------------------------------------------------------------------
// Kernel C: per-row plain sum of NCHP partials -> invZ
// ---------------------------------------------------------------------------
__global__ void reduce_kernel() {
    const int row = blockIdx.x;
    const int t = threadIdx.x;    // 512
    float s = 0.f;
    const float* p = &g_psum[(size_t)row * NCHP];
    for (int i = t; i < NCHP; i += 512) s += p[i];
    __shared__ float ss[512];
    ss[t] = s;
    __syncthreads();
    for (int stride = 256; stride > 0; stride >>= 1) {
        if (t < stride) ss[t] += ss[t + stride];
        __syncthreads();
    }
    if (t == 0) g_invZ[row] = 1.f / ss[0];
}

// ---------------------------------------------------------------------------
extern "C" void kernel_launch(void* const* d_in, const int* in_sizes, int n_in,
                              void* d_out, int out_size) {
    const int*   x     = (const int*)d_in[0];
    const float* noise = (const float*)d_in[1];
    const float* emb   = (const float*)d_in[2];
    const float* W_ih  = (const float*)d_in[3];
    /* d_in[4] = W_hh — dead: h0 == 0 */
    const float* b_ih  = (const float*)d_in[5];
    const float* b_hh  = (const float*)d_in[6];
    const float* fc_w  = (const float*)d_in[7];
    const float* fc_b  = (const float*)d_in[8];
    float* out = (float*)d_out;

    const int smemA = (384 * WPAD + A_ROWS * CIN) * 4;
    cudaFuncSetAttribute(lstm_kernel, cudaFuncAttributeMaxDynamicSharedMemorySize, smemA);
    cudaFuncSetAttribute(gemm_tc<1>, cudaFuncAttributeMaxDynamicSharedMemorySize, SMEM_GEMM);
    cudaFuncSetAttribute(gemm_tc<2>, cudaFuncAttributeMaxDynamicSharedMemorySize, SMEM_GEMM);

    lstm_kernel<<<BATCH / A_ROWS, 256, smemA>>>(x, noise, emb, W_ih, b_ih, b_hh);
    gemm_tc<1><<<NCH2, 256, SMEM_GEMM>>>(fc_w, fc_b, out);
    reduce_kernel<<<BATCH, 512>>>();
    gemm_tc<2><<<NCH2, 256, SMEM_GEMM>>>(fc_w, fc_b, out);
}